// round 10
// baseline (speedup 1.0000x reference)
#include <cuda_runtime.h>
#include <cstdint>

#define BB 16
#define SS 2048
#define NC 8
#define NT 256
#define NW (NT / 32)            // 8 warps per CTA
#define CSZ 8                   // CTAs per cluster (= per row)
#define GRIDN (BB * CSZ)        // 128 CTAs
#define LOG2E 1.4426950408889634f
#define T1V 100.0f
#define EPSV 1e-8f

__device__ __forceinline__ float ex2(float x) {
    float y; asm("ex2.approx.ftz.f32 %0, %1;" : "=f"(y) : "f"(x)); return y;
}
__device__ __forceinline__ float flog(float x) {
    float y; asm("lg2.approx.ftz.f32 %0, %1;" : "=f"(y) : "f"(x));
    return y * 0.6931471805599453f;
}
__device__ __forceinline__ uint32_t smem_u32(const void* p) {
    uint32_t a;
    asm("{ .reg .u64 t; cvta.to.shared.u64 t, %1; cvt.u32.u64 %0, t; }" : "=r"(a) : "l"(p));
    return a;
}
__device__ __forceinline__ uint32_t mapa_rank(uint32_t addr, uint32_t rank) {
    uint32_t r;
    asm("mapa.shared::cluster.u32 %0, %1, %2;" : "=r"(r) : "r"(addr), "r"(rank));
    return r;
}
__device__ __forceinline__ float ld_dsmem(uint32_t addr) {
    float v;
    asm volatile("ld.shared::cluster.f32 %0, [%1];" : "=f"(v) : "r"(addr));
    return v;
}
__device__ __forceinline__ uint32_t ctarank() {
    uint32_t r; asm("mov.u32 %0, %%cluster_ctarank;" : "=r"(r)); return r;
}
#define CLUSTER_SYNC() do { \
    asm volatile("barrier.cluster.arrive.aligned;" ::: "memory"); \
    asm volatile("barrier.cluster.wait.aligned;"   ::: "memory"); \
} while (0)

// Cross-block state (no allocations). Replay-safe.
__device__ double   g_partials[GRIDN];
__device__ unsigned g_ticket;           // last block resets to 0 each run

__global__ __launch_bounds__(NT) __cluster_dims__(CSZ, 1, 1)
void hawkes_kernel(const float* __restrict__ ts,
                   const int*   __restrict__ ms,
                   const float* __restrict__ mu,
                   const float* __restrict__ alphas,
                   const float* __restrict__ beta,
                   float*       __restrict__ out)
{
    __shared__ float  AB[NC * NC];       // alphas[m][c] * beta[c]
    __shared__ float  colsum[NC];
    __shared__ float  mu_s[NC];
    __shared__ float  Wagg[NW][NC + 1];  // per-warp channel sums (anchored at own Tw)
    __shared__ float  WT[NW];            // per-warp anchor timestamps
    __shared__ float  inclW[NW][NC + 1]; // inclusive cross-warp prefix
    __shared__ float  pubV[NC];          // this CTA's aggregate (DSMEM-visible)
    __shared__ float  pubT[1];           // its anchor timestamp
    __shared__ float  cpV[NC];           // prefix over previous CTAs in cluster
    __shared__ float  cpT[1];
    __shared__ double wsum[NW];

    const int bx    = blockIdx.x;
    const int row   = bx >> 3;           // / CSZ
    const int crank = (int)ctarank();    // 0..7 within row
    const int t     = threadIdx.x;
    const int w     = t >> 5;
    const int lane  = t & 31;

    // ---- Per-thread params (const cache) ----
    float bl2[NC];
    #pragma unroll
    for (int c = 0; c < NC; c++) bl2[c] = __ldg(&beta[c]) * LOG2E;

    if (t < NC * NC) AB[t] = alphas[t] * __ldg(&beta[t & (NC - 1)]);
    if (t < NC) {
        float s = 0.f;
        #pragma unroll
        for (int k = 0; k < NC; k++) s += alphas[k * NC + t];
        colsum[t] = s;
        mu_s[t]   = mu[t];
    }

    // ---- This thread's single event (coalesced) ----
    const int   li    = row * SS + crank * NT + t;
    const float ti    = ts[li];
    const int   m     = ms[li];
    const bool  valid = (ti > 0.f);

    // Warp anchor = last event time in warp (sorted ascending)
    const float Tw = __shfl_sync(0xffffffffu, ti, 31);

    // ---- One-hot event weight anchored at Tw (exponent <= 0) ----
    const float ev = valid ? ex2(bl2[m] * (ti - Tw)) : 0.f;
    float V[NC];
    #pragma unroll
    for (int c = 0; c < NC; c++) V[c] = 0.f;
    if (valid) V[m] = ev;

    // ---- Warp inclusive Kogge-Stone: PLAIN ADDS (common anchor) ----
    #pragma unroll
    for (int off = 1; off < 32; off <<= 1) {
        float Vp[NC];
        #pragma unroll
        for (int c = 0; c < NC; c++) Vp[c] = __shfl_up_sync(0xffffffffu, V[c], off);
        if (lane >= off) {
            #pragma unroll
            for (int c = 0; c < NC; c++) V[c] += Vp[c];
        }
    }
    if (lane == 31) {
        #pragma unroll
        for (int c = 0; c < NC; c++) Wagg[w][c] = V[c];
        WT[w] = Tw;
    }
    __syncthreads();

    // ---- Serial scan over 8 warps; decay factors precomputed (FMA-only chain) ----
    if (t < NC) {
        const int c = t;
        float dec[NW];
        dec[0] = 0.f;
        #pragma unroll
        for (int ww = 1; ww < NW; ww++)
            dec[ww] = ex2(bl2[c] * (WT[ww - 1] - WT[ww]));   // independent ex2s
        float run = Wagg[0][c];
        inclW[0][c] = run;
        #pragma unroll
        for (int ww = 1; ww < NW; ww++) {
            run = fmaf(run, dec[ww], Wagg[ww][c]);
            inclW[ww][c] = run;
        }
        pubV[c] = run;                       // CTA aggregate, anchored at WT[7]
        if (c == 0) pubT[0] = WT[NW - 1];
    }
    __syncthreads();

    // ---- Publish to cluster; read previous CTAs' aggregates via DSMEM ----
    CLUSTER_SYNC();

    if (t < NC) {
        const int c = t;
        // prefetch peer values (independent DSMEM loads), then combine
        float pv[CSZ - 1], pt[CSZ - 1];
        const uint32_t aV = smem_u32(&pubV[c]);
        const uint32_t aT = smem_u32(&pubT[0]);
        for (int k = 0; k < crank; k++) {
            pv[k] = ld_dsmem(mapa_rank(aV, (uint32_t)k));
            pt[k] = ld_dsmem(mapa_rank(aT, (uint32_t)k));
        }
        float run = 0.f, Tprev = 0.f;
        for (int k = 0; k < crank; k++) {
            run = pv[k] + run * ex2(bl2[c] * (Tprev - pt[k]));  // Tprev <= pt[k]
            Tprev = pt[k];
        }
        cpV[c] = run;                         // anchored at pt[crank-1]
        if (c == 0) cpT[0] = Tprev;
    }
    __syncthreads();
    CLUSTER_SYNC();   // peers may still be reading our pubV; don't race ahead

    // ---- Exclusive state S anchored at Tw ----
    float S[NC];
    #pragma unroll
    for (int c = 0; c < NC; c++) {
        float p = __shfl_up_sync(0xffffffffu, V[c], 1);
        S[c] = (lane == 0) ? 0.f : p;
    }
    if (w > 0) {
        const float Tp = WT[w - 1];
        #pragma unroll
        for (int c = 0; c < NC; c++)
            S[c] += inclW[w - 1][c] * ex2(bl2[c] * (Tp - Tw));
    }
    if (crank > 0) {
        const float Tc = cpT[0];
        #pragma unroll
        for (int c = 0; c < NC; c++)
            S[c] += cpV[c] * ex2(bl2[c] * (Tc - Tw));
    }

    // ---- Per-event log-likelihood term (independent) ----
    double acc = 0.0;
    if (valid) {
        float lam = mu_s[m];
        #pragma unroll
        for (int c = 0; c < NC; c++)
            lam += AB[m * NC + c] * S[c] * ex2(bl2[c] * (Tw - ti)); // exponent >= 0, warp-bounded
        float contrib = flog(lam + EPSV)
                      - colsum[m] * (1.f - ex2(-bl2[m] * (T1V - ti)));
        acc = (double)contrib;
    }

    // ---- Reduce: warp shfl -> block -> ticketed global finalize ----
    #pragma unroll
    for (int off = 16; off > 0; off >>= 1)
        acc += __shfl_down_sync(0xffffffffu, acc, off);
    if (lane == 0) wsum[w] = acc;
    __syncthreads();

    if (t == 0) {
        double s = 0.0;
        #pragma unroll
        for (int ww = 0; ww < NW; ww++) s += wsum[ww];
        g_partials[bx] = s;
        __threadfence();
        unsigned tk = atomicAdd(&g_ticket, 1u);
        if (tk == GRIDN - 1) {                // last block finalizes, fixed order
            __threadfence();
            double tot = 0.0;
            #pragma unroll 16
            for (int i = 0; i < GRIDN; i++) tot += __ldcg(&g_partials[i]);
            double musum = 0.0;
            #pragma unroll
            for (int c = 0; c < NC; c++) musum += (double)mu_s[c];
            out[0] = (float)(tot - musum * (double)T1V);
            __threadfence();
            g_ticket = 0;                     // reset for next graph replay
        }
    }
}

extern "C" void kernel_launch(void* const* d_in, const int* in_sizes, int n_in,
                              void* d_out, int out_size)
{
    const float* ts     = (const float*)d_in[0];
    const int*   ms     = (const int*)  d_in[1];
    const float* mu     = (const float*)d_in[2];
    const float* alphas = (const float*)d_in[3];
    const float* beta   = (const float*)d_in[4];
    float*       out    = (float*)d_out;

    hawkes_kernel<<<GRIDN, NT>>>(ts, ms, mu, alphas, beta, out);
}

// round 11
// speedup vs baseline: 1.0615x; 1.0615x over previous
#include <cuda_runtime.h>

#define BB 16
#define SS 2048
#define NC 8
#define NT 256
#define NW (NT / 32)           // 8 warps per CTA
#define RPB 8                  // segments (CTAs) per row
#define GRIDN (BB * RPB)       // 128 CTAs
#define LOG2E 1.4426950408889634f
#define T1V 100.0f
#define EPSV 1e-8f

__device__ __forceinline__ float ex2(float x) {
    float y; asm("ex2.approx.ftz.f32 %0, %1;" : "=f"(y) : "f"(x)); return y;
}
__device__ __forceinline__ float flog(float x) {
    float y; asm("lg2.approx.ftz.f32 %0, %1;" : "=f"(y) : "f"(x));
    return y * 0.6931471805599453f;
}

// Cross-block state (no allocations). Replay-safe: tickets reset by their winners.
__device__ double   g_part[GRIDN];
__device__ double   g_rowsum[BB];
__device__ unsigned g_rowtick[BB];
__device__ unsigned g_ticket;

__global__ __launch_bounds__(NT)
void hawkes_kernel(const float* __restrict__ ts,
                   const int*   __restrict__ ms,
                   const float* __restrict__ mu,
                   const float* __restrict__ alphas,
                   const float* __restrict__ beta,
                   float*       __restrict__ out)
{
    __shared__ float  AB[NC * NC];       // alphas[m][c] * beta[c]
    __shared__ float  colsum[NC];
    __shared__ float  mu_s[NC];
    __shared__ float  Rw[NW][NC + 1];    // per-warp redundant-prefix partials
    __shared__ float  Wagg[NW][NC + 1];  // per-warp scan totals (anchored at own Tw)
    __shared__ float  WT[NW];            // per-warp anchors
    __shared__ float  Ew[NW][NC + 1];    // exclusive base per warp, anchored at WT[w]
    __shared__ double wsum[NW];

    const int bx   = blockIdx.x;
    const int row  = bx >> 3;            // / RPB
    const int seg  = bx & (RPB - 1);
    const int t    = threadIdx.x;
    const int w    = t >> 5;
    const int lane = t & 31;

    const float* tsr = ts + row * SS;
    const int*   msr = ms + row * SS;

    // ---- Issue ALL loads up front (max MLP, one scoreboard wait) ----
    // Redundant-prefix events: k*NT+t for k<seg; indices always in-bounds (<2048).
    float tj[RPB - 1]; int mj[RPB - 1];
    #pragma unroll
    for (int k = 0; k < RPB - 1; k++) {
        tj[k] = tsr[k * NT + t];
        mj[k] = msr[k * NT + t];
    }
    const int   li = seg * NT + t;
    const float ti = tsr[li];
    const int   m  = msr[li];
    const float Tpre = (seg > 0) ? tsr[seg * NT - 1] : 0.f;   // prior-segment anchor

    // ---- Per-thread params (L1-broadcast) + smem staging ----
    float bl2[NC];
    #pragma unroll
    for (int c = 0; c < NC; c++) bl2[c] = __ldg(&beta[c]) * LOG2E;
    if (t < NC * NC) AB[t] = alphas[t] * __ldg(&beta[t & (NC - 1)]);
    if (t < NC) {
        float s = 0.f;
        #pragma unroll
        for (int k = 0; k < NC; k++) s += alphas[k * NC + t];
        colsum[t] = s;
        mu_s[t]   = mu[t];
    }

    // ---- Redundant prefix reduce, anchored at Tpre (exponents <= 0; ftz ok) ----
    float R[NC];
    #pragma unroll
    for (int c = 0; c < NC; c++) R[c] = 0.f;
    #pragma unroll
    for (int k = 0; k < RPB - 1; k++) {
        if (k < seg && tj[k] > 0.f)
            R[mj[k]] += ex2(bl2[mj[k]] * (tj[k] - Tpre));
    }
    #pragma unroll
    for (int off = 16; off > 0; off >>= 1) {
        #pragma unroll
        for (int c = 0; c < NC; c++)
            R[c] += __shfl_down_sync(0xffffffffu, R[c], off);
    }
    if (lane == 0) {
        #pragma unroll
        for (int c = 0; c < NC; c++) Rw[w][c] = R[c];
    }

    // ---- Own event, one-hot anchored at warp anchor Tw (32-event span, tiny exp) ----
    const bool  valid = (ti > 0.f);
    const float Tw    = __shfl_sync(0xffffffffu, ti, 31);
    const float ev    = valid ? ex2(bl2[m] * (ti - Tw)) : 0.f;
    float V[NC];
    #pragma unroll
    for (int c = 0; c < NC; c++) V[c] = 0.f;
    if (valid) V[m] = ev;

    // ---- Warp inclusive Kogge-Stone: plain adds (common anchor) ----
    #pragma unroll
    for (int off = 1; off < 32; off <<= 1) {
        float Vp[NC];
        #pragma unroll
        for (int c = 0; c < NC; c++) Vp[c] = __shfl_up_sync(0xffffffffu, V[c], off);
        if (lane >= off) {
            #pragma unroll
            for (int c = 0; c < NC; c++) V[c] += Vp[c];
        }
    }
    if (lane == 31) {
        #pragma unroll
        for (int c = 0; c < NC; c++) Wagg[w][c] = V[c];
        WT[w] = Tw;
    }
    __syncthreads();

    // ---- t<8: finish redundant reduce + serial cross-warp chain (FMA-only) ----
    if (t < NC) {
        const int c = t;
        float P = 0.f;
        #pragma unroll
        for (int ww = 0; ww < NW; ww++) P += Rw[ww][c];
        if (seg == 0) P = 0.f;

        float dec[NW];                       // independent ex2s, pipeline through MUFU
        dec[0] = ex2(bl2[c] * (Tpre - WT[0]));
        #pragma unroll
        for (int ww = 1; ww < NW; ww++)
            dec[ww] = ex2(bl2[c] * (WT[ww - 1] - WT[ww]));

        float run = P * dec[0];              // exclusive base at WT[0]
        Ew[0][c] = run;
        #pragma unroll
        for (int ww = 1; ww < NW; ww++) {
            run = fmaf(run + Wagg[ww - 1][c], dec[ww], 0.f);
            Ew[ww][c] = run;
        }
    }
    __syncthreads();

    // ---- Exclusive state S at Tw; per-event lambda (independent) ----
    float S[NC];
    #pragma unroll
    for (int c = 0; c < NC; c++) {
        float p = __shfl_up_sync(0xffffffffu, V[c], 1);
        S[c] = Ew[w][c] + ((lane == 0) ? 0.f : p);
    }

    double acc = 0.0;
    if (valid) {
        float lam = mu_s[m];
        #pragma unroll
        for (int c = 0; c < NC; c++)
            lam += AB[m * NC + c] * S[c] * ex2(bl2[c] * (Tw - ti));  // exp >= 0, warp-bounded
        float contrib = flog(lam + EPSV)
                      - colsum[m] * (1.f - ex2(-bl2[m] * (T1V - ti)));
        acc = (double)contrib;
    }

    // ---- Reduce: warp -> block -> row ticket -> global ticket ----
    #pragma unroll
    for (int off = 16; off > 0; off >>= 1)
        acc += __shfl_down_sync(0xffffffffu, acc, off);
    if (lane == 0) wsum[w] = acc;
    __syncthreads();

    if (t == 0) {
        double s = 0.0;
        #pragma unroll
        for (int ww = 0; ww < NW; ww++) s += wsum[ww];
        g_part[bx] = s;
        __threadfence();
        unsigned rt = atomicAdd(&g_rowtick[row], 1u);
        if (rt == RPB - 1) {                 // last segment of this row
            __threadfence();
            double rs = 0.0;
            #pragma unroll
            for (int k = 0; k < RPB; k++) rs += __ldcg(&g_part[row * RPB + k]);
            g_rowsum[row] = rs;
            g_rowtick[row] = 0;              // reset for next replay (all 8 arrived)
            __threadfence();
            unsigned gt = atomicAdd(&g_ticket, 1u);
            if (gt == BB - 1) {              // last row finalizes, fixed order
                __threadfence();
                double tot = 0.0;
                #pragma unroll
                for (int r = 0; r < BB; r++) tot += __ldcg(&g_rowsum[r]);
                double musum = 0.0;
                #pragma unroll
                for (int c = 0; c < NC; c++) musum += (double)mu_s[c];
                out[0] = (float)(tot - musum * (double)T1V);
                __threadfence();
                g_ticket = 0;                // reset for next replay
            }
        }
    }
}

extern "C" void kernel_launch(void* const* d_in, const int* in_sizes, int n_in,
                              void* d_out, int out_size)
{
    const float* ts     = (const float*)d_in[0];
    const int*   ms     = (const int*)  d_in[1];
    const float* mu     = (const float*)d_in[2];
    const float* alphas = (const float*)d_in[3];
    const float* beta   = (const float*)d_in[4];
    float*       out    = (float*)d_out;

    hawkes_kernel<<<GRIDN, NT>>>(ts, ms, mu, alphas, beta, out);
}

// round 14
// speedup vs baseline: 1.6692x; 1.5725x over previous
#include <cuda_runtime.h>

#define BB 16
#define SS 2048
#define NC 8
#define NT 512
#define NW (NT / 32)           // 16 warps
#define CHUNK 4                // SS / NT
#define LOG2E 1.4426950408889634f
#define T1V 100.0f
#define EPSV 1e-8f

__device__ __forceinline__ float ex2(float x) {
    float y; asm("ex2.approx.ftz.f32 %0, %1;" : "=f"(y) : "f"(x)); return y;
}
__device__ __forceinline__ float flog(float x) {
    float y; asm("lg2.approx.ftz.f32 %0, %1;" : "=f"(y) : "f"(x));
    return y * 0.6931471805599453f;
}

// Cross-block state (no allocations). Replay-safe.
__device__ double   g_partials[BB];
__device__ unsigned g_ticket;          // winner resets to 0 each run

__global__ __launch_bounds__(NT)
void hawkes_kernel(const float* __restrict__ ts,
                   const int*   __restrict__ ms,
                   const float* __restrict__ mu,
                   const float* __restrict__ alphas,
                   const float* __restrict__ beta,
                   float*       __restrict__ out)
{
    __shared__ float  AB[NC * NC];       // alphas[m][c] * beta[c]
    __shared__ float  colsum[NC];        // sum_k alphas[k][c]
    __shared__ float  mu_s[NC];
    __shared__ float  Wagg[NW][NC + 1];  // per-warp channel sums (anchored at own Tw)
    __shared__ float  WT[NW];            // per-warp anchor timestamps
    __shared__ float  inclW[NW][NC + 1]; // inclusive cross-warp prefix
    __shared__ float  wsum[NW];          // per-warp float partials

    const int b    = blockIdx.x;         // one block per batch row
    const int t    = threadIdx.x;
    const int w    = t >> 5;
    const int lane = t & 31;

    // ---- Per-thread params (const cache; no barrier needed) ----
    float bl2[NC];
    #pragma unroll
    for (int c = 0; c < NC; c++) bl2[c] = __ldg(&beta[c]) * LOG2E;

    // ---- Stage small params into smem (covered by the scan barrier below) ----
    if (t < NC * NC) AB[t] = alphas[t] * __ldg(&beta[t & (NC - 1)]);
    if (t < NC) {
        float s = 0.f;
        #pragma unroll
        for (int k = 0; k < NC; k++) s += alphas[k * NC + t];
        colsum[t] = s;
        mu_s[t]   = mu[t];
    }

    // ---- Load this thread's 4 events (LDG.128, coalesced) ----
    float tloc[CHUNK];
    int   mloc[CHUNK];
    *(float4*)tloc = ((const float4*)(ts + b * SS))[t];
    *(int4*)mloc   = ((const int4*)  (ms + b * SS))[t];

    // Warp anchor = last event time in warp (sorted ascending)
    const float Tw = __shfl_sync(0xffffffffu, tloc[CHUNK - 1], 31);

    // ---- Anchored event weights (independent ex2s) ----
    float ev[CHUNK];
    #pragma unroll
    for (int j = 0; j < CHUNK; j++)
        ev[j] = (tloc[j] > 0.f) ? ex2(bl2[mloc[j]] * (tloc[j] - Tw)) : 0.f;

    // ---- Chunk channel sums ----
    float V[NC];
    #pragma unroll
    for (int c = 0; c < NC; c++) V[c] = 0.f;
    #pragma unroll
    for (int j = 0; j < CHUNK; j++) V[mloc[j]] += ev[j];

    // ---- Warp inclusive Kogge-Stone: PLAIN ADDS (common anchor) ----
    #pragma unroll
    for (int off = 1; off < 32; off <<= 1) {
        float Vp[NC];
        #pragma unroll
        for (int c = 0; c < NC; c++) Vp[c] = __shfl_up_sync(0xffffffffu, V[c], off);
        if (lane >= off) {
            #pragma unroll
            for (int c = 0; c < NC; c++) V[c] += Vp[c];
        }
    }
    if (lane == 31) {
        #pragma unroll
        for (int c = 0; c < NC; c++) Wagg[w][c] = V[c];
        WT[w] = Tw;
    }
    __syncthreads();

    // ---- Serial rescale-scan across 16 warps (thread c owns class c) ----
    // Decay factors precomputed as INDEPENDENT ex2s; chain is FMA-only.
    if (t < NC) {
        const int c = t;
        float dec[NW];
        #pragma unroll
        for (int ww = 1; ww < NW; ww++)
            dec[ww] = ex2(bl2[c] * (WT[ww - 1] - WT[ww]));   // pipelined through MUFU
        float run = Wagg[0][c];
        inclW[0][c] = run;
        #pragma unroll
        for (int ww = 1; ww < NW; ww++) {
            run = fmaf(run, dec[ww], Wagg[ww][c]);
            inclW[ww][c] = run;
        }
    }
    __syncthreads();

    // ---- Exclusive prefix state S anchored at Tw ----
    float S[NC];
    {
        float Ve[NC];
        #pragma unroll
        for (int c = 0; c < NC; c++) {
            float p = __shfl_up_sync(0xffffffffu, V[c], 1);
            Ve[c] = (lane == 0) ? 0.f : p;
        }
        if (w > 0) {
            const float Tp = WT[w - 1];
            #pragma unroll
            for (int c = 0; c < NC; c++)
                S[c] = Ve[c] + inclW[w - 1][c] * ex2(bl2[c] * (Tp - Tw));
        } else {
            #pragma unroll
            for (int c = 0; c < NC; c++) S[c] = Ve[c];
        }
    }

    // ---- Per-event log-likelihood terms (independent; float accumulation) ----
    float acc = 0.f;
    #pragma unroll
    for (int j = 0; j < CHUNK; j++) {
        const float ti = tloc[j];
        const int   m  = mloc[j];
        if (ti > 0.f) {
            float lam = mu_s[m];
            #pragma unroll
            for (int c = 0; c < NC; c++)
                lam += AB[m * NC + c] * S[c] * ex2(bl2[c] * (Tw - ti)); // exp >= 0, warp-bounded
            acc += flog(lam + EPSV)
                 - colsum[m] * (1.f - ex2(-bl2[m] * (T1V - ti)));
        }
        S[m] += ev[j];   // event j becomes source for later events in chunk
    }

    // ---- Warp reduce (float), publish per-warp partials ----
    #pragma unroll
    for (int off = 16; off > 0; off >>= 1)
        acc += __shfl_down_sync(0xffffffffu, acc, off);
    if (lane == 0) wsum[w] = acc;
    __syncthreads();

    // ---- Warp 0: block partial + ticketed PARALLEL finalize ----
    if (w == 0) {
        float v = (lane < NW) ? wsum[lane] : 0.f;
        #pragma unroll
        for (int off = 8; off > 0; off >>= 1)
            v += __shfl_down_sync(0xffffffffu, v, off);     // lanes 16+ are 0

        unsigned tk = 0;
        if (lane == 0) {
            g_partials[b] = (double)v;
            __threadfence();
            tk = atomicAdd(&g_ticket, 1u);
        }
        tk = __shfl_sync(0xffffffffu, tk, 0);

        if (tk == BB - 1) {                 // last block: one lane per row partial
            __threadfence();
            double dv = (lane < BB) ? (double)__ldcg(&g_partials[lane]) : 0.0;
            #pragma unroll
            for (int off = 8; off > 0; off >>= 1)
                dv += __shfl_down_sync(0xffffffffu, dv, off);   // deterministic tree
            if (lane == 0) {
                double musum = 0.0;
                #pragma unroll
                for (int c = 0; c < NC; c++) musum += (double)mu_s[c];
                out[0] = (float)(dv - musum * (double)T1V);
                __threadfence();
                g_ticket = 0;               // reset for next graph replay
            }
        }
    }
}

extern "C" void kernel_launch(void* const* d_in, const int* in_sizes, int n_in,
                              void* d_out, int out_size)
{
    const float* ts     = (const float*)d_in[0];
    const int*   ms     = (const int*)  d_in[1];
    const float* mu     = (const float*)d_in[2];
    const float* alphas = (const float*)d_in[3];
    const float* beta   = (const float*)d_in[4];
    float*       out    = (float*)d_out;

    hawkes_kernel<<<BB, NT>>>(ts, ms, mu, alphas, beta, out);
}